// round 2
// baseline (speedup 1.0000x reference)
#include <cuda_runtime.h>
#include <cstdint>

// HyperConnections fused kernel, round 2: 3 CTAs/SM + cp.async prefetch.
// dot(norm_h, w) identity folds LN + projections into one 28-value reduction:
//   dot = rstd*(sum h*g*w - mu*sum g*w) + sum beta_ln*w
// g_W / g_S1 / g_S2 are token-independent, precomputed once per launch.

constexpr int DIMC  = 2048;
constexpr int RATEC = 4;
constexpr int NW    = 5;          // alpha cols 1..4 (col 0 unused) + beta_fn
constexpr int TPB   = 256;
constexpr int VEC   = DIMC / TPB; // 8 floats / thread / stream
constexpr float DSCALE = 0.01f;
constexpr float EPSF   = 1e-5f;

__device__ float g_W[NW][DIMC];   // gamma[d] * w_j[d]
__device__ float g_S1[NW];        // sum gamma*w
__device__ float g_S2[NW];        // sum ln_beta*w

__device__ __forceinline__ void cp_async16(uint32_t smem_addr, const void* gptr) {
    asm volatile("cp.async.cg.shared.global [%0], [%1], 16;"
                 :: "r"(smem_addr), "l"(gptr));
}

__global__ void precompute_k(const float* __restrict__ gamma,
                             const float* __restrict__ lbeta,
                             const float* __restrict__ afn,   // (DIM, 5)
                             const float* __restrict__ bfn) { // (DIM,)
    const int tid = threadIdx.x;   // 512 threads
    float s1[NW], s2[NW];
#pragma unroll
    for (int j = 0; j < NW; j++) { s1[j] = 0.f; s2[j] = 0.f; }
    for (int d = tid; d < DIMC; d += 512) {
        const float g = gamma[d], b = lbeta[d];
#pragma unroll
        for (int j = 0; j < NW; j++) {
            const float w = (j < 4) ? afn[d * 5 + j + 1] : bfn[d];
            g_W[j][d] = g * w;
            s1[j] += g * w;
            s2[j] += b * w;
        }
    }
#pragma unroll
    for (int j = 0; j < NW; j++) {
#pragma unroll
        for (int o = 16; o; o >>= 1) {
            s1[j] += __shfl_xor_sync(0xffffffffu, s1[j], o);
            s2[j] += __shfl_xor_sync(0xffffffffu, s2[j], o);
        }
    }
    __shared__ float sm[16][2 * NW];
    const int w = tid >> 5, lane = tid & 31;
    if (lane == 0) {
#pragma unroll
        for (int j = 0; j < NW; j++) { sm[w][j] = s1[j]; sm[w][NW + j] = s2[j]; }
    }
    __syncthreads();
    if (tid < 2 * NW) {
        float s = 0.f;
#pragma unroll
        for (int ww = 0; ww < 16; ww++) s += sm[ww][tid];
        if (tid < NW) g_S1[tid] = s;
        else          g_S2[tid - NW] = s;
    }
}

__global__ __launch_bounds__(TPB, 3) void hyper_k(
    const float* __restrict__ h,    // (NTOK, RATE, DIM)
    const float* __restrict__ h_o,  // (NTOK, DIM)
    const float* __restrict__ sA,   // static_alpha (RATE, 5)
    const float* __restrict__ sB,   // static_beta  (RATE,)
    float* __restrict__ out)        // (NTOK, RATE, DIM)
{
    __shared__ float s_h23[2 * DIMC];            // 16 KB: streams 2,3
    __shared__ float s_ho[DIMC];                 // 8 KB:  h_o
    __shared__ float s_part[8][RATEC * 7];
    __shared__ float s_fin[RATEC * 7];

    const int t   = blockIdx.x;
    const int tid = threadIdx.x;
    const size_t hbase = (size_t)t * (RATEC * DIMC);
    const int d0 = tid * VEC;

    // ---- Fire-and-forget prefetch: streams 2,3 (16 KB contiguous) + h_o ----
    {
        const uint32_t sdst = (uint32_t)__cvta_generic_to_shared(s_h23);
        const float4* src = (const float4*)(h + hbase + 2 * DIMC);
#pragma unroll
        for (int k = 0; k < 4; k++) {
            const int idx = tid + k * TPB;               // 0..1023 float4s
            cp_async16(sdst + idx * 16, src + idx);
        }
        const uint32_t sdo = (uint32_t)__cvta_generic_to_shared(s_ho);
        const float4* srco = (const float4*)(h_o + (size_t)t * DIMC);
#pragma unroll
        for (int k = 0; k < 2; k++) {
            const int idx = tid + k * TPB;               // 0..511 float4s
            cp_async16(sdo + idx * 16, srco + idx);
        }
        asm volatile("cp.async.commit_group;" ::: "memory");
    }

    float acc[RATEC][7];   // per-stream: sum, sum2, 5 dots
    float h01[2][VEC];

    // ---- Part A: streams 0,1 via LDG into registers ----
#pragma unroll
    for (int n = 0; n < 2; n++) {
        const float4* src = (const float4*)(h + hbase + n * DIMC + d0);
        const float4 a = src[0], b = src[1];
        h01[n][0]=a.x; h01[n][1]=a.y; h01[n][2]=a.z; h01[n][3]=a.w;
        h01[n][4]=b.x; h01[n][5]=b.y; h01[n][6]=b.z; h01[n][7]=b.w;
        float sh = 0.f, sh2 = 0.f;
#pragma unroll
        for (int i = 0; i < VEC; i++) {
            sh += h01[n][i];
            sh2 = fmaf(h01[n][i], h01[n][i], sh2);
        }
        acc[n][0] = sh; acc[n][1] = sh2;
    }
    // dots for streams 0,1 (overlaps cp.async DRAM latency)
#pragma unroll
    for (int j = 0; j < NW; j++) {
        const float4* wp = (const float4*)(&g_W[j][d0]);
        const float4 a = wp[0], b = wp[1];
        const float wv[VEC] = {a.x, a.y, a.z, a.w, b.x, b.y, b.z, b.w};
        float s0 = 0.f, s1 = 0.f;
#pragma unroll
        for (int i = 0; i < VEC; i++) {
            s0 = fmaf(h01[0][i], wv[i], s0);
            s1 = fmaf(h01[1][i], wv[i], s1);
        }
        acc[0][2 + j] = s0; acc[1][2 + j] = s1;
    }

    asm volatile("cp.async.wait_group 0;" ::: "memory");
    __syncthreads();

    // ---- Part B: streams 2,3 from smem (L1-latency, not DRAM) ----
    float h23[2][VEC];
#pragma unroll
    for (int n = 0; n < 2; n++) {
        const float4* sp = (const float4*)(&s_h23[n * DIMC + d0]);
        const float4 a = sp[0], b = sp[1];
        h23[n][0]=a.x; h23[n][1]=a.y; h23[n][2]=a.z; h23[n][3]=a.w;
        h23[n][4]=b.x; h23[n][5]=b.y; h23[n][6]=b.z; h23[n][7]=b.w;
        float sh = 0.f, sh2 = 0.f;
#pragma unroll
        for (int i = 0; i < VEC; i++) {
            sh += h23[n][i];
            sh2 = fmaf(h23[n][i], h23[n][i], sh2);
        }
        acc[2 + n][0] = sh; acc[2 + n][1] = sh2;
    }
#pragma unroll
    for (int j = 0; j < NW; j++) {
        const float4* wp = (const float4*)(&g_W[j][d0]);   // L1 hit
        const float4 a = wp[0], b = wp[1];
        const float wv[VEC] = {a.x, a.y, a.z, a.w, b.x, b.y, b.z, b.w};
        float s2 = 0.f, s3 = 0.f;
#pragma unroll
        for (int i = 0; i < VEC; i++) {
            s2 = fmaf(h23[0][i], wv[i], s2);
            s3 = fmaf(h23[1][i], wv[i], s3);
        }
        acc[2][2 + j] = s2; acc[3][2 + j] = s3;
    }

    // ---- Block reduction of 28 values ----
    float* pf = &acc[0][0];
#pragma unroll
    for (int v = 0; v < RATEC * 7; v++) {
#pragma unroll
        for (int o = 16; o; o >>= 1)
            pf[v] += __shfl_xor_sync(0xffffffffu, pf[v], o);
    }
    const int w = tid >> 5, lane = tid & 31;
    if (lane == 0) {
#pragma unroll
        for (int v = 0; v < RATEC * 7; v++) s_part[w][v] = pf[v];
    }
    __syncthreads();
    if (tid < RATEC * 7) {
        float s = 0.f;
#pragma unroll
        for (int ww = 0; ww < 8; ww++) s += s_part[ww][tid];
        s_fin[tid] = s;
    }
    __syncthreads();

    // ---- Reconstruct alpha (4x4 used block) and beta ----
    float alpha[RATEC][RATEC];   // alpha[m][n] = full_alpha[m][n+1]
    float beta[RATEC];
    const float invD = 1.0f / DIMC;
#pragma unroll
    for (int m = 0; m < RATEC; m++) {
        const float mu   = s_fin[m * 7 + 0] * invD;
        const float var  = s_fin[m * 7 + 1] * invD - mu * mu;
        const float rstd = rsqrtf(var + EPSF);
#pragma unroll
        for (int j = 0; j < NW; j++) {
            const float dot = rstd * (s_fin[m * 7 + 2 + j] - mu * g_S1[j]) + g_S2[j];
            const float dyn = dot * DSCALE;
            if (j < 4) alpha[m][j] = dyn + sA[m * 5 + j + 1];
            else       beta[m]     = dyn + sB[m];
        }
    }

    // ---- Phase 2: mix + depth connection (h all in regs, h_o from smem) ----
    const float4* hop = (const float4*)(&s_ho[d0]);
    const float4 o0 = hop[0], o1 = hop[1];
    const float hov[VEC] = {o0.x, o0.y, o0.z, o0.w, o1.x, o1.y, o1.z, o1.w};
#pragma unroll
    for (int n = 0; n < RATEC; n++) {
        float ov[VEC];
#pragma unroll
        for (int i = 0; i < VEC; i++) {
            float a2 = hov[i] * beta[n];
            a2 = fmaf(alpha[0][n], h01[0][i], a2);
            a2 = fmaf(alpha[1][n], h01[1][i], a2);
            a2 = fmaf(alpha[2][n], h23[0][i], a2);
            a2 = fmaf(alpha[3][n], h23[1][i], a2);
            ov[i] = a2;
        }
        float4* dst = (float4*)(out + hbase + n * DIMC + d0);
        dst[0] = make_float4(ov[0], ov[1], ov[2], ov[3]);
        dst[1] = make_float4(ov[4], ov[5], ov[6], ov[7]);
    }
}

extern "C" void kernel_launch(void* const* d_in, const int* in_sizes, int n_in,
                              void* d_out, int out_size) {
    const float* h     = (const float*)d_in[0];
    const float* h_o   = (const float*)d_in[1];
    const float* gamma = (const float*)d_in[2];
    const float* lbeta = (const float*)d_in[3];
    const float* afn   = (const float*)d_in[4];
    const float* bfn   = (const float*)d_in[5];
    const float* sA    = (const float*)d_in[6];
    const float* sB    = (const float*)d_in[7];
    float* out = (float*)d_out;

    const int ntok = in_sizes[1] / DIMC;   // b*l from h_o element count

    precompute_k<<<1, 512>>>(gamma, lbeta, afn, bfn);
    hyper_k<<<ntok, TPB>>>(h, h_o, sA, sB, out);
}